// round 12
// baseline (speedup 1.0000x reference)
#include <cuda_runtime.h>
#include <cuda_fp16.h>
#include <math.h>
#include <stdint.h>

typedef uint32_t u32;
typedef unsigned long long u64;

#define LC 20
#define KGRID 1024

// ---- dynamic smem layout (byte offsets) ----
#define OFF_A0H 0          // 128 rows * 20 u32 (stride 80B) = 10240 (hi tile only)
#define OFF_B0  10240      // 2kc*8nt*32lane * uint2 = 4096  (fp16)
#define OFF_B1F 14336      // 4kc*8nt*32lane * uint2 = 8192  (fp16)
#define OFF_W2  22528      // 64 * float4
#define OFF_B1P 23552      // 32 * float2
#define OFF_HG0 23808      // 512 floats
#define OFF_SC  25856      // 3 floats
#define SMEM_BYTES 25872

// pack two floats into f16x2 (v0 -> lower half), RN
__device__ __forceinline__ u32 packh(float v0, float v1) {
    u32 h;
    asm("cvt.rn.f16x2.f32 %0, %1, %2;" : "=r"(h) : "f"(v1), "f"(v0));
    return h;
}
// masked split: hi keeps 11 significand bits (exact fp16), lo = exact residual.
__device__ __forceinline__ void split2m(float v0, float v1, u32 &hp, u32 &lp) {
    float f0 = __uint_as_float(__float_as_uint(v0) & 0xFFFFE000u);
    float f1 = __uint_as_float(__float_as_uint(v1) & 0xFFFFE000u);
    hp = packh(f0, f1);
    lp = packh(v0 - f0, v1 - f1);
}

// packed f32x2 helpers
__device__ __forceinline__ u64 pk2(float a, float b) {
    u64 r; asm("mov.b64 %0, {%1, %2};" : "=l"(r) : "f"(a), "f"(b)); return r;
}
__device__ __forceinline__ void upk2(u64 v, float &a, float &b) {
    asm("mov.b64 {%0, %1}, %2;" : "=f"(a), "=f"(b) : "l"(v));
}
__device__ __forceinline__ void ffma2(u64 &acc, u64 a, u64 b) {
    asm("fma.rn.f32x2 %0, %1, %2, %0;" : "+l"(acc) : "l"(a), "l"(b));
}

__device__ __forceinline__ void mma16816(float d[4], const u32 a[4], u32 b0, u32 b1) {
    asm volatile(
        "mma.sync.aligned.m16n8k16.row.col.f32.f16.f16.f32 "
        "{%0,%1,%2,%3}, {%4,%5,%6,%7}, {%8,%9}, {%0,%1,%2,%3};"
        : "+f"(d[0]), "+f"(d[1]), "+f"(d[2]), "+f"(d[3])
        : "r"(a[0]), "r"(a[1]), "r"(a[2]), "r"(a[3]), "r"(b0), "r"(b1));
}

// ---- feature gather: RBF-bilinear (regular grid) + 2 hashgrid levels ----
__device__ __forceinline__ void gather_feats(float2 p,
                                             const float* __restrict__ lc0,
                                             const float* __restrict__ hg1,
                                             const float* shg0,
                                             float* h0)
{
    {
        float gx = p.x * 1023.0f, gy = p.y * 1023.0f;
        int ix = (int)floorf(gx); ix = max(0, min(ix, 1022));
        int iy = (int)floorf(gy); iy = max(0, min(iy, 1022));
        float fx = gx - (float)ix, fy = gy - (float)iy;
        // weights sum to 1 (+-1ulp); reference's normalize shifts them ~1e-7 -> dropped
        float w00 = (1.0f - fx) * (1.0f - fy);
        float w01 = (1.0f - fx) * fy;
        float w10 = fx * (1.0f - fy);
        float w11 = fx * fy;
        u64 W00 = pk2(w00, w00), W01 = pk2(w01, w01);
        u64 W10 = pk2(w10, w10), W11 = pk2(w11, w11);
        const float4* r0 = (const float4*)(lc0 + (size_t)(ix * KGRID + iy) * LC);
        const float4* r1 = (const float4*)(lc0 + (size_t)((ix + 1) * KGRID + iy) * LC);
        #pragma unroll
        for (int q = 0; q < 5; q++) {
            float4 c00 = r0[q], c01 = r0[q + 5];
            float4 c10 = r1[q], c11 = r1[q + 5];
            u64 a01 = 0ull, a23 = 0ull;
            ffma2(a01, pk2(c00.x, c00.y), W00); ffma2(a23, pk2(c00.z, c00.w), W00);
            ffma2(a01, pk2(c01.x, c01.y), W01); ffma2(a23, pk2(c01.z, c01.w), W01);
            ffma2(a01, pk2(c10.x, c10.y), W10); ffma2(a23, pk2(c10.z, c10.w), W10);
            ffma2(a01, pk2(c11.x, c11.y), W11); ffma2(a23, pk2(c11.z, c11.w), W11);
            upk2(a01, h0[4 * q + 0], h0[4 * q + 1]);
            upk2(a23, h0[4 * q + 2], h0[4 * q + 3]);
        }
    }
    {
        float gx = p.x * 15.0f, gy = p.y * 15.0f;
        int ix = (int)floorf(gx); ix = max(0, min(ix, 14));
        int iy = (int)floorf(gy); iy = max(0, min(iy, 14));
        float fx = gx - (float)ix, fy = gy - (float)iy;
        float w00 = (1.0f - fx) * (1.0f - fy), w01 = (1.0f - fx) * fy;
        float w10 = fx * (1.0f - fy),          w11 = fx * fy;
        const float2* t = (const float2*)shg0;
        float2 c00 = t[ix * 16 + iy],       c01 = t[ix * 16 + iy + 1];
        float2 c10 = t[(ix + 1) * 16 + iy], c11 = t[(ix + 1) * 16 + iy + 1];
        h0[20] = w00 * c00.x + w01 * c01.x + w10 * c10.x + w11 * c11.x;
        h0[21] = w00 * c00.y + w01 * c01.y + w10 * c10.y + w11 * c11.y;
    }
    {
        float gx = p.x * 2047.0f, gy = p.y * 2047.0f;
        int ix = (int)floorf(gx); ix = max(0, min(ix, 2046));
        int iy = (int)floorf(gy); iy = max(0, min(iy, 2046));
        float fx = gx - (float)ix, fy = gy - (float)iy;
        float w00 = (1.0f - fx) * (1.0f - fy), w01 = (1.0f - fx) * fy;
        float w10 = fx * (1.0f - fy),          w11 = fx * fy;
        const float2* t = (const float2*)hg1;
        float2 c00 = t[ix * 2048 + iy],       c01 = t[ix * 2048 + iy + 1];
        float2 c10 = t[(ix + 1) * 2048 + iy], c11 = t[(ix + 1) * 2048 + iy + 1];
        h0[22] = w00 * c00.x + w01 * c01.x + w10 * c10.x + w11 * c11.x;
        h0[23] = w00 * c00.y + w01 * c01.y + w10 * c10.y + w11 * c11.y;
    }
}

__global__ void __launch_bounds__(128, 3)
rbf_mma_kernel(const float2* __restrict__ x,
               const float* __restrict__ hg0g, const float* __restrict__ hg1,
               const float* __restrict__ lc0,  const float* __restrict__ lcbg,
               const float* __restrict__ W0g, const float* __restrict__ b0g,
               const float* __restrict__ W1g, const float* __restrict__ b1g,
               const float* __restrict__ W2g, const float* __restrict__ b2g,
               const float* __restrict__ a0g, const float* __restrict__ a1g,
               const float* __restrict__ a2g,
               float* __restrict__ out, int n, int ntiles)
{
    extern __shared__ char base[];
    const int tid = threadIdx.x;
    const int wid = tid >> 5, lane = tid & 31;
    const int g = lane >> 2, t = lane & 3;
    const float a0 = a0g[0], a1 = a1g[0], a2 = a2g[0];

    u32*    sA0h = (u32*)(base + OFF_A0H);
    uint2*  sB0  = (uint2*)(base + OFF_B0);
    uint2*  sB1  = (uint2*)(base + OFF_B1F);
    float4* sW2  = (float4*)(base + OFF_W2);
    float2* sb1p = (float2*)(base + OFF_B1P);
    float*  shg0 = (float*)(base + OFF_HG0);
    float*  ssc  = (float*)(base + OFF_SC);

    // ---- one-time init ----
    for (int k = tid; k < 512; k += 128) shg0[k] = hg0g[k];
    if (tid < 64)
        sW2[tid] = make_float4(a2 * W2g[tid], a2 * W2g[64 + tid], a2 * W2g[128 + tid], 0.0f);
    if (tid < 32) {
        int nt_ = tid >> 2, t_ = tid & 3;
        int c0 = nt_ * 8 + 2 * t_;
        sb1p[tid] = make_float2(a1 * b1g[c0], a1 * b1g[c0 + 1]);
    }
    if (tid < 3) ssc[tid] = a2 * b2g[tid];

    // constant A0 row tail (cols 24..31): bias 1.0 at col 24, zeros elsewhere.
    {
        u32* rowh = sA0h + tid * 20;
        rowh[12] = 0x00003C00u; rowh[13] = 0u; rowh[14] = 0u; rowh[15] = 0u;
        rowh[16] = rowh[17] = rowh[18] = rowh[19] = 0u;
    }

    // B0 fragments (fp16): B0[k][n]; k<24: a0*W0[n][k];
    // k==24: a0*(b0[n]+lcb@W0[n]); else 0
    for (int s = tid; s < 512; s += 128) {
        int ln = s & 31, nt_ = (s >> 5) & 7, kc = s >> 8;
        int gg = ln >> 2, tt = ln & 3;
        int nn = nt_ * 8 + gg;
        int k0 = kc * 16 + 2 * tt;
        float w[4];
        #pragma unroll
        for (int q = 0; q < 4; q++) {
            int k = k0 + (q >> 1) * 8 + (q & 1);
            float v;
            if (k < 24) v = a0 * W0g[nn * 24 + k];
            else if (k == 24) {
                float acc = b0g[nn];
                for (int kk = 0; kk < 24; kk++) acc += lcbg[kk] * W0g[nn * 24 + kk];
                v = a0 * acc;
            } else v = 0.0f;
            w[q] = v;
        }
        sB0[s] = make_uint2(packh(w[0], w[1]), packh(w[2], w[3]));
    }
    // B1 fragments (fp16): B1[k][n] = a1*W1[n][k]
    for (int s = tid; s < 1024; s += 128) {
        int ln = s & 31, nt_ = (s >> 5) & 7, kc = s >> 8;
        int gg = ln >> 2, tt = ln & 3;
        int nn = nt_ * 8 + gg;
        int k0 = kc * 16 + 2 * tt;
        float w0v = a1 * W1g[nn * 64 + k0];
        float w1v = a1 * W1g[nn * 64 + k0 + 1];
        float w2v = a1 * W1g[nn * 64 + k0 + 8];
        float w3v = a1 * W1g[nn * 64 + k0 + 9];
        sB1[s] = make_uint2(packh(w0v, w1v), packh(w2v, w3v));
    }
    __syncthreads();

    const float c0s = ssc[0], c1s = ssc[1], c2s = ssc[2];
    const int gw = blockIdx.x * 4 + wid;
    const int nw = gridDim.x * 4;
    const int rbase = wid * 32;

    for (int tile = gw; tile < ntiles; tile += nw) {
        int i = tile * 32 + lane;
        int ii = (i < n) ? i : (n - 1);

        float h0[24];
        gather_feats(x[ii], lc0, hg1, shg0, h0);

        // ---- write this lane's A0 row cols 0..23, fp16 RN (hi only) ----
        {
            u32 rh[12];
            #pragma unroll
            for (int q = 0; q < 12; q++)
                rh[q] = packh(h0[2 * q], h0[2 * q + 1]);
            uint4* rh4 = (uint4*)(sA0h + (rbase + lane) * 20);
            #pragma unroll
            for (int q = 0; q < 3; q++)
                rh4[q] = make_uint4(rh[4 * q], rh[4 * q + 1], rh[4 * q + 2], rh[4 * q + 3]);
        }
        __syncwarp();

        // ---- load A0 fragments (hi only) for BOTH m halves ----
        u32 Ah[2][2][4];   // [m][kc][4]
        #pragma unroll
        for (int m = 0; m < 2; m++) {
            int ridx = (rbase + 16 * m + g) * 20 + t;
            #pragma unroll
            for (int kc = 0; kc < 2; kc++) {
                Ah[m][kc][0] = sA0h[ridx + 8 * kc];
                Ah[m][kc][1] = sA0h[ridx + 8 * kc + 160];
                Ah[m][kc][2] = sA0h[ridx + 8 * kc + 4];
                Ah[m][kc][3] = sA0h[ridx + 8 * kc + 164];
            }
        }
        __syncwarp();   // all frag reads done before next tile's writes

        // ---- layer 0: nt-pairs x both m = 4 independent chains, A hi-only ----
        u32 A1h[2][4][4], A1l[2][4][4];   // [m][kc1][4]
        #pragma unroll
        for (int ntp = 0; ntp < 4; ntp++) {
            float d[2][2][4];             // [ntq][m][4]
            #pragma unroll
            for (int q_ = 0; q_ < 2; q_++)
                #pragma unroll
                for (int m = 0; m < 2; m++)
                    d[q_][m][0] = d[q_][m][1] = d[q_][m][2] = d[q_][m][3] = 0.f;
            #pragma unroll
            for (int kc = 0; kc < 2; kc++) {
                uint2 Ba = sB0[(kc * 8 + 2 * ntp) * 32 + lane];
                uint2 Bb = sB0[(kc * 8 + 2 * ntp + 1) * 32 + lane];
                mma16816(d[0][0], Ah[0][kc], Ba.x, Ba.y);
                mma16816(d[1][0], Ah[0][kc], Bb.x, Bb.y);
                mma16816(d[0][1], Ah[1][kc], Ba.x, Ba.y);
                mma16816(d[1][1], Ah[1][kc], Bb.x, Bb.y);
            }
            #pragma unroll
            for (int q_ = 0; q_ < 2; q_++) {
                int nt = 2 * ntp + q_;
                int kc1 = nt >> 1, hf = nt & 1;
                #pragma unroll
                for (int m = 0; m < 2; m++) {
                    float v0 = fmaxf(d[q_][m][0], 0.f), v1 = fmaxf(d[q_][m][1], 0.f);
                    float v2 = fmaxf(d[q_][m][2], 0.f), v3 = fmaxf(d[q_][m][3], 0.f);
                    split2m(v0, v1, A1h[m][kc1][hf ? 2 : 0], A1l[m][kc1][hf ? 2 : 0]);
                    split2m(v2, v3, A1h[m][kc1][hf ? 3 : 1], A1l[m][kc1][hf ? 3 : 1]);
                }
            }
        }

        // ---- layer 1 + fused output layer, 2-term A split, 4-chain interleave ----
        float o[2][2][3];
        #pragma unroll
        for (int m = 0; m < 2; m++)
            #pragma unroll
            for (int r = 0; r < 2; r++)
                o[m][r][0] = o[m][r][1] = o[m][r][2] = 0.0f;

        #pragma unroll
        for (int ntp = 0; ntp < 4; ntp++) {
            float d[2][2][4];
            #pragma unroll
            for (int q_ = 0; q_ < 2; q_++)
                #pragma unroll
                for (int m = 0; m < 2; m++)
                    d[q_][m][0] = d[q_][m][1] = d[q_][m][2] = d[q_][m][3] = 0.f;
            #pragma unroll
            for (int kc = 0; kc < 4; kc++) {
                uint2 Ba = sB1[(kc * 8 + 2 * ntp) * 32 + lane];
                uint2 Bb = sB1[(kc * 8 + 2 * ntp + 1) * 32 + lane];
                mma16816(d[0][0], A1h[0][kc], Ba.x, Ba.y);
                mma16816(d[1][0], A1h[0][kc], Bb.x, Bb.y);
                mma16816(d[0][1], A1h[1][kc], Ba.x, Ba.y);
                mma16816(d[1][1], A1h[1][kc], Bb.x, Bb.y);
                mma16816(d[0][0], A1l[0][kc], Ba.x, Ba.y);
                mma16816(d[1][0], A1l[0][kc], Bb.x, Bb.y);
                mma16816(d[0][1], A1l[1][kc], Ba.x, Ba.y);
                mma16816(d[1][1], A1l[1][kc], Bb.x, Bb.y);
            }
            #pragma unroll
            for (int q_ = 0; q_ < 2; q_++) {
                int nt = 2 * ntp + q_;
                float2 bp = sb1p[nt * 4 + t];
                float4 wa = sW2[nt * 8 + 2 * t];
                float4 wb = sW2[nt * 8 + 2 * t + 1];
                #pragma unroll
                for (int m = 0; m < 2; m++) {
                    float v0 = fmaxf(d[q_][m][0] + bp.x, 0.f);
                    float v1 = fmaxf(d[q_][m][1] + bp.y, 0.f);
                    float v2 = fmaxf(d[q_][m][2] + bp.x, 0.f);
                    float v3 = fmaxf(d[q_][m][3] + bp.y, 0.f);
                    o[m][0][0] += v0 * wa.x + v1 * wb.x;
                    o[m][0][1] += v0 * wa.y + v1 * wb.y;
                    o[m][0][2] += v0 * wa.z + v1 * wb.z;
                    o[m][1][0] += v2 * wa.x + v3 * wb.x;
                    o[m][1][1] += v2 * wa.y + v3 * wb.y;
                    o[m][1][2] += v2 * wa.z + v3 * wb.z;
                }
            }
        }

        // reduce partials across the 4 lanes of each group (cols are t-partitioned)
        #pragma unroll
        for (int m = 0; m < 2; m++)
            #pragma unroll
            for (int r = 0; r < 2; r++)
                #pragma unroll
                for (int c = 0; c < 3; c++) {
                    float v = o[m][r][c];
                    v += __shfl_xor_sync(0xFFFFFFFFu, v, 1);
                    v += __shfl_xor_sync(0xFFFFFFFFu, v, 2);
                    o[m][r][c] = v;
                }

        if (t == 0) {
            #pragma unroll
            for (int m = 0; m < 2; m++)
                #pragma unroll
                for (int r = 0; r < 2; r++) {
                    int idx = tile * 32 + 16 * m + 8 * r + g;
                    if (idx < n) {
                        out[3 * idx + 0] = o[m][r][0] + c0s;
                        out[3 * idx + 1] = o[m][r][1] + c1s;
                        out[3 * idx + 2] = o[m][r][2] + c2s;
                    }
                }
        }
    }
}

extern "C" void kernel_launch(void* const* d_in, const int* in_sizes, int n_in,
                              void* d_out, int out_size)
{
    const float2* x    = (const float2*)d_in[0];
    const float*  hg0  = (const float*)d_in[1];
    const float*  hg1  = (const float*)d_in[2];
    // d_in[3] = kc0 (regular grid, analytic), d_in[4] = ks0 (== K-1)
    const float*  lc0  = (const float*)d_in[5];
    const float*  lcb0 = (const float*)d_in[6];
    const float*  W0   = (const float*)d_in[7];
    const float*  b0   = (const float*)d_in[8];
    const float*  W1   = (const float*)d_in[9];
    const float*  b1   = (const float*)d_in[10];
    const float*  W2   = (const float*)d_in[11];
    const float*  b2   = (const float*)d_in[12];
    const float*  a0   = (const float*)d_in[13];
    const float*  a1   = (const float*)d_in[14];
    const float*  a2   = (const float*)d_in[15];
    float* out = (float*)d_out;

    const int n = in_sizes[0] / 2;
    const int ntiles = (n + 31) / 32;
    int grid = 444;                       // 148 SMs x 3 blocks
    int maxg = (ntiles + 3) / 4;
    if (grid > maxg) grid = maxg;

    cudaFuncSetAttribute(rbf_mma_kernel, cudaFuncAttributeMaxDynamicSharedMemorySize, SMEM_BYTES);
    rbf_mma_kernel<<<grid, 128, SMEM_BYTES>>>(x, hg0, hg1, lc0, lcb0,
                                              W0, b0, W1, b1, W2, b2,
                                              a0, a1, a2, out, n, ntiles);
}

// round 13
// speedup vs baseline: 1.4699x; 1.4699x over previous
#include <cuda_runtime.h>
#include <cuda_fp16.h>
#include <math.h>
#include <stdint.h>

typedef uint32_t u32;
typedef unsigned long long u64;

#define LC 20
#define KGRID 1024

// ---- dynamic smem layout (byte offsets) ----
#define OFF_A0H 0          // 128 rows * 20 u32 (stride 80B) = 10240 (hi tile only)
#define OFF_B0  10240      // 2kc*8nt*32lane * uint2 = 4096  (fp16)
#define OFF_B1F 14336      // 4kc*8nt*32lane * uint2 = 8192  (fp16)
#define OFF_W2  22528      // 64 * float4
#define OFF_B1P 23552      // 32 * float2
#define OFF_HG0 23808      // 512 floats
#define OFF_SC  25856      // 3 floats
#define SMEM_BYTES 25872

// pack two floats into f16x2 (v0 -> lower half), RN
__device__ __forceinline__ u32 packh(float v0, float v1) {
    u32 h;
    asm("cvt.rn.f16x2.f32 %0, %1, %2;" : "=r"(h) : "f"(v1), "f"(v0));
    return h;
}
// masked split: hi keeps 11 significand bits (exact fp16), lo = exact residual.
__device__ __forceinline__ void split2m(float v0, float v1, u32 &hp, u32 &lp) {
    float f0 = __uint_as_float(__float_as_uint(v0) & 0xFFFFE000u);
    float f1 = __uint_as_float(__float_as_uint(v1) & 0xFFFFE000u);
    hp = packh(f0, f1);
    lp = packh(v0 - f0, v1 - f1);
}

// packed f32x2 helpers
__device__ __forceinline__ u64 pk2(float a, float b) {
    u64 r; asm("mov.b64 %0, {%1, %2};" : "=l"(r) : "f"(a), "f"(b)); return r;
}
__device__ __forceinline__ void upk2(u64 v, float &a, float &b) {
    asm("mov.b64 {%0, %1}, %2;" : "=f"(a), "=f"(b) : "l"(v));
}
__device__ __forceinline__ void ffma2(u64 &acc, u64 a, u64 b) {
    asm("fma.rn.f32x2 %0, %1, %2, %0;" : "+l"(acc) : "l"(a), "l"(b));
}

__device__ __forceinline__ void mma16816(float d[4], const u32 a[4], u32 b0, u32 b1) {
    asm volatile(
        "mma.sync.aligned.m16n8k16.row.col.f32.f16.f16.f32 "
        "{%0,%1,%2,%3}, {%4,%5,%6,%7}, {%8,%9}, {%0,%1,%2,%3};"
        : "+f"(d[0]), "+f"(d[1]), "+f"(d[2]), "+f"(d[3])
        : "r"(a[0]), "r"(a[1]), "r"(a[2]), "r"(a[3]), "r"(b0), "r"(b1));
}

// ---- feature gather: RBF-bilinear (regular grid) + 2 hashgrid levels ----
__device__ __forceinline__ void gather_feats(float2 p,
                                             const float* __restrict__ lc0,
                                             const float* __restrict__ hg1,
                                             const float* shg0,
                                             float* h0)
{
    {
        float gx = p.x * 1023.0f, gy = p.y * 1023.0f;
        int ix = (int)floorf(gx); ix = max(0, min(ix, 1022));
        int iy = (int)floorf(gy); iy = max(0, min(iy, 1022));
        float fx = gx - (float)ix, fy = gy - (float)iy;
        // weights sum to 1 (+-1ulp); reference's normalize shifts them ~1e-7 -> dropped
        float w00 = (1.0f - fx) * (1.0f - fy);
        float w01 = (1.0f - fx) * fy;
        float w10 = fx * (1.0f - fy);
        float w11 = fx * fy;
        u64 W00 = pk2(w00, w00), W01 = pk2(w01, w01);
        u64 W10 = pk2(w10, w10), W11 = pk2(w11, w11);
        const float4* r0 = (const float4*)(lc0 + (size_t)(ix * KGRID + iy) * LC);
        const float4* r1 = (const float4*)(lc0 + (size_t)((ix + 1) * KGRID + iy) * LC);
        #pragma unroll
        for (int q = 0; q < 5; q++) {
            float4 c00 = r0[q], c01 = r0[q + 5];
            float4 c10 = r1[q], c11 = r1[q + 5];
            u64 a01 = 0ull, a23 = 0ull;
            ffma2(a01, pk2(c00.x, c00.y), W00); ffma2(a23, pk2(c00.z, c00.w), W00);
            ffma2(a01, pk2(c01.x, c01.y), W01); ffma2(a23, pk2(c01.z, c01.w), W01);
            ffma2(a01, pk2(c10.x, c10.y), W10); ffma2(a23, pk2(c10.z, c10.w), W10);
            ffma2(a01, pk2(c11.x, c11.y), W11); ffma2(a23, pk2(c11.z, c11.w), W11);
            upk2(a01, h0[4 * q + 0], h0[4 * q + 1]);
            upk2(a23, h0[4 * q + 2], h0[4 * q + 3]);
        }
    }
    {
        float gx = p.x * 15.0f, gy = p.y * 15.0f;
        int ix = (int)floorf(gx); ix = max(0, min(ix, 14));
        int iy = (int)floorf(gy); iy = max(0, min(iy, 14));
        float fx = gx - (float)ix, fy = gy - (float)iy;
        float w00 = (1.0f - fx) * (1.0f - fy), w01 = (1.0f - fx) * fy;
        float w10 = fx * (1.0f - fy),          w11 = fx * fy;
        const float2* t = (const float2*)shg0;
        float2 c00 = t[ix * 16 + iy],       c01 = t[ix * 16 + iy + 1];
        float2 c10 = t[(ix + 1) * 16 + iy], c11 = t[(ix + 1) * 16 + iy + 1];
        h0[20] = w00 * c00.x + w01 * c01.x + w10 * c10.x + w11 * c11.x;
        h0[21] = w00 * c00.y + w01 * c01.y + w10 * c10.y + w11 * c11.y;
    }
    {
        float gx = p.x * 2047.0f, gy = p.y * 2047.0f;
        int ix = (int)floorf(gx); ix = max(0, min(ix, 2046));
        int iy = (int)floorf(gy); iy = max(0, min(iy, 2046));
        float fx = gx - (float)ix, fy = gy - (float)iy;
        float w00 = (1.0f - fx) * (1.0f - fy), w01 = (1.0f - fx) * fy;
        float w10 = fx * (1.0f - fy),          w11 = fx * fy;
        const float2* t = (const float2*)hg1;
        float2 c00 = t[ix * 2048 + iy],       c01 = t[ix * 2048 + iy + 1];
        float2 c10 = t[(ix + 1) * 2048 + iy], c11 = t[(ix + 1) * 2048 + iy + 1];
        h0[22] = w00 * c00.x + w01 * c01.x + w10 * c10.x + w11 * c11.x;
        h0[23] = w00 * c00.y + w01 * c01.y + w10 * c10.y + w11 * c11.y;
    }
}

__global__ void __launch_bounds__(128, 3)
rbf_mma_kernel(const float2* __restrict__ x,
               const float* __restrict__ hg0g, const float* __restrict__ hg1,
               const float* __restrict__ lc0,  const float* __restrict__ lcbg,
               const float* __restrict__ W0g, const float* __restrict__ b0g,
               const float* __restrict__ W1g, const float* __restrict__ b1g,
               const float* __restrict__ W2g, const float* __restrict__ b2g,
               const float* __restrict__ a0g, const float* __restrict__ a1g,
               const float* __restrict__ a2g,
               float* __restrict__ out, int n, int ntiles)
{
    extern __shared__ char base[];
    const int tid = threadIdx.x;
    const int wid = tid >> 5, lane = tid & 31;
    const int g = lane >> 2, t = lane & 3;
    const float a0 = a0g[0], a1 = a1g[0], a2 = a2g[0];

    u32*    sA0h = (u32*)(base + OFF_A0H);
    uint2*  sB0  = (uint2*)(base + OFF_B0);
    uint2*  sB1  = (uint2*)(base + OFF_B1F);
    float4* sW2  = (float4*)(base + OFF_W2);
    float2* sb1p = (float2*)(base + OFF_B1P);
    float*  shg0 = (float*)(base + OFF_HG0);
    float*  ssc  = (float*)(base + OFF_SC);

    // ---- one-time init ----
    for (int k = tid; k < 512; k += 128) shg0[k] = hg0g[k];
    if (tid < 64)
        sW2[tid] = make_float4(a2 * W2g[tid], a2 * W2g[64 + tid], a2 * W2g[128 + tid], 0.0f);
    if (tid < 32) {
        int nt_ = tid >> 2, t_ = tid & 3;
        int c0 = nt_ * 8 + 2 * t_;
        sb1p[tid] = make_float2(a1 * b1g[c0], a1 * b1g[c0 + 1]);
    }
    if (tid < 3) ssc[tid] = a2 * b2g[tid];

    // constant A0 row tail (cols 24..31): bias 1.0 at col 24, zeros elsewhere.
    {
        u32* rowh = sA0h + tid * 20;
        rowh[12] = 0x00003C00u; rowh[13] = 0u; rowh[14] = 0u; rowh[15] = 0u;
        rowh[16] = rowh[17] = rowh[18] = rowh[19] = 0u;
    }

    // B0 fragments (fp16): B0[k][n]; k<24: a0*W0[n][k];
    // k==24: a0*(b0[n]+lcb@W0[n]); else 0
    for (int s = tid; s < 512; s += 128) {
        int ln = s & 31, nt_ = (s >> 5) & 7, kc = s >> 8;
        int gg = ln >> 2, tt = ln & 3;
        int nn = nt_ * 8 + gg;
        int k0 = kc * 16 + 2 * tt;
        float w[4];
        #pragma unroll
        for (int q = 0; q < 4; q++) {
            int k = k0 + (q >> 1) * 8 + (q & 1);
            float v;
            if (k < 24) v = a0 * W0g[nn * 24 + k];
            else if (k == 24) {
                float acc = b0g[nn];
                for (int kk = 0; kk < 24; kk++) acc += lcbg[kk] * W0g[nn * 24 + kk];
                v = a0 * acc;
            } else v = 0.0f;
            w[q] = v;
        }
        sB0[s] = make_uint2(packh(w[0], w[1]), packh(w[2], w[3]));
    }
    // B1 fragments (fp16): B1[k][n] = a1*W1[n][k]
    for (int s = tid; s < 1024; s += 128) {
        int ln = s & 31, nt_ = (s >> 5) & 7, kc = s >> 8;
        int gg = ln >> 2, tt = ln & 3;
        int nn = nt_ * 8 + gg;
        int k0 = kc * 16 + 2 * tt;
        float w0v = a1 * W1g[nn * 64 + k0];
        float w1v = a1 * W1g[nn * 64 + k0 + 1];
        float w2v = a1 * W1g[nn * 64 + k0 + 8];
        float w3v = a1 * W1g[nn * 64 + k0 + 9];
        sB1[s] = make_uint2(packh(w0v, w1v), packh(w2v, w3v));
    }
    __syncthreads();

    const float c0s = ssc[0], c1s = ssc[1], c2s = ssc[2];
    const int gw = blockIdx.x * 4 + wid;
    const int nw = gridDim.x * 4;
    const int rbase = wid * 32;

    for (int tile = gw; tile < ntiles; tile += nw) {
        int i = tile * 32 + lane;
        int ii = (i < n) ? i : (n - 1);

        float h0[24];
        gather_feats(x[ii], lc0, hg1, shg0, h0);

        // ---- write this lane's A0 row cols 0..23, fp16 RN (hi only) ----
        {
            u32 rh[12];
            #pragma unroll
            for (int q = 0; q < 12; q++)
                rh[q] = packh(h0[2 * q], h0[2 * q + 1]);
            uint4* rh4 = (uint4*)(sA0h + (rbase + lane) * 20);
            #pragma unroll
            for (int q = 0; q < 3; q++)
                rh4[q] = make_uint4(rh[4 * q], rh[4 * q + 1], rh[4 * q + 2], rh[4 * q + 3]);
        }
        __syncwarp();

        // ---- load A0 fragments (hi only) for BOTH m halves ----
        u32 Ah[2][2][4];   // [m][kc][4]
        #pragma unroll
        for (int m = 0; m < 2; m++) {
            int ridx = (rbase + 16 * m + g) * 20 + t;
            #pragma unroll
            for (int kc = 0; kc < 2; kc++) {
                Ah[m][kc][0] = sA0h[ridx + 8 * kc];
                Ah[m][kc][1] = sA0h[ridx + 8 * kc + 160];
                Ah[m][kc][2] = sA0h[ridx + 8 * kc + 4];
                Ah[m][kc][3] = sA0h[ridx + 8 * kc + 164];
            }
        }
        __syncwarp();   // all frag reads done before next tile's writes

        // ---- layer 0: nt-pairs x both m = 4 independent chains, A hi-only ----
        u32 A1h[2][4][4], A1l[2][4][4];   // [m][kc1][4]
        #pragma unroll
        for (int ntp = 0; ntp < 4; ntp++) {
            float d[2][2][4];             // [ntq][m][4]
            #pragma unroll
            for (int q_ = 0; q_ < 2; q_++)
                #pragma unroll
                for (int m = 0; m < 2; m++)
                    d[q_][m][0] = d[q_][m][1] = d[q_][m][2] = d[q_][m][3] = 0.f;
            #pragma unroll
            for (int kc = 0; kc < 2; kc++) {
                uint2 Ba = sB0[(kc * 8 + 2 * ntp) * 32 + lane];
                uint2 Bb = sB0[(kc * 8 + 2 * ntp + 1) * 32 + lane];
                mma16816(d[0][0], Ah[0][kc], Ba.x, Ba.y);
                mma16816(d[1][0], Ah[0][kc], Bb.x, Bb.y);
                mma16816(d[0][1], Ah[1][kc], Ba.x, Ba.y);
                mma16816(d[1][1], Ah[1][kc], Bb.x, Bb.y);
            }
            #pragma unroll
            for (int q_ = 0; q_ < 2; q_++) {
                int nt = 2 * ntp + q_;
                int kc1 = nt >> 1, hf = nt & 1;
                #pragma unroll
                for (int m = 0; m < 2; m++) {
                    float v0 = fmaxf(d[q_][m][0], 0.f), v1 = fmaxf(d[q_][m][1], 0.f);
                    float v2 = fmaxf(d[q_][m][2], 0.f), v3 = fmaxf(d[q_][m][3], 0.f);
                    split2m(v0, v1, A1h[m][kc1][hf ? 2 : 0], A1l[m][kc1][hf ? 2 : 0]);
                    split2m(v2, v3, A1h[m][kc1][hf ? 3 : 1], A1l[m][kc1][hf ? 3 : 1]);
                }
            }
        }

        // ---- layer 1 + fused output layer, 2-term A split, 4-chain interleave ----
        float o[2][2][3];
        #pragma unroll
        for (int m = 0; m < 2; m++)
            #pragma unroll
            for (int r = 0; r < 2; r++)
                o[m][r][0] = o[m][r][1] = o[m][r][2] = 0.0f;

        #pragma unroll
        for (int ntp = 0; ntp < 4; ntp++) {
            float d[2][2][4];
            #pragma unroll
            for (int q_ = 0; q_ < 2; q_++)
                #pragma unroll
                for (int m = 0; m < 2; m++)
                    d[q_][m][0] = d[q_][m][1] = d[q_][m][2] = d[q_][m][3] = 0.f;
            #pragma unroll
            for (int kc = 0; kc < 4; kc++) {
                uint2 Ba = sB1[(kc * 8 + 2 * ntp) * 32 + lane];
                uint2 Bb = sB1[(kc * 8 + 2 * ntp + 1) * 32 + lane];
                mma16816(d[0][0], A1h[0][kc], Ba.x, Ba.y);
                mma16816(d[1][0], A1h[0][kc], Bb.x, Bb.y);
                mma16816(d[0][1], A1h[1][kc], Ba.x, Ba.y);
                mma16816(d[1][1], A1h[1][kc], Bb.x, Bb.y);
                mma16816(d[0][0], A1l[0][kc], Ba.x, Ba.y);
                mma16816(d[1][0], A1l[0][kc], Bb.x, Bb.y);
                mma16816(d[0][1], A1l[1][kc], Ba.x, Ba.y);
                mma16816(d[1][1], A1l[1][kc], Bb.x, Bb.y);
            }
            #pragma unroll
            for (int q_ = 0; q_ < 2; q_++) {
                int nt = 2 * ntp + q_;
                float2 bp = sb1p[nt * 4 + t];
                float4 wa = sW2[nt * 8 + 2 * t];
                float4 wb = sW2[nt * 8 + 2 * t + 1];
                #pragma unroll
                for (int m = 0; m < 2; m++) {
                    float v0 = fmaxf(d[q_][m][0] + bp.x, 0.f);
                    float v1 = fmaxf(d[q_][m][1] + bp.y, 0.f);
                    float v2 = fmaxf(d[q_][m][2] + bp.x, 0.f);
                    float v3 = fmaxf(d[q_][m][3] + bp.y, 0.f);
                    o[m][0][0] += v0 * wa.x + v1 * wb.x;
                    o[m][0][1] += v0 * wa.y + v1 * wb.y;
                    o[m][0][2] += v0 * wa.z + v1 * wb.z;
                    o[m][1][0] += v2 * wa.x + v3 * wb.x;
                    o[m][1][1] += v2 * wa.y + v3 * wb.y;
                    o[m][1][2] += v2 * wa.z + v3 * wb.z;
                }
            }
        }

        // reduce partials across the 4 lanes of each group (cols are t-partitioned)
        #pragma unroll
        for (int m = 0; m < 2; m++)
            #pragma unroll
            for (int r = 0; r < 2; r++)
                #pragma unroll
                for (int c = 0; c < 3; c++) {
                    float v = o[m][r][c];
                    v += __shfl_xor_sync(0xFFFFFFFFu, v, 1);
                    v += __shfl_xor_sync(0xFFFFFFFFu, v, 2);
                    o[m][r][c] = v;
                }

        if (t == 0) {
            #pragma unroll
            for (int m = 0; m < 2; m++)
                #pragma unroll
                for (int r = 0; r < 2; r++) {
                    int idx = tile * 32 + 16 * m + 8 * r + g;
                    if (idx < n) {
                        out[3 * idx + 0] = o[m][r][0] + c0s;
                        out[3 * idx + 1] = o[m][r][1] + c1s;
                        out[3 * idx + 2] = o[m][r][2] + c2s;
                    }
                }
        }
    }
}

extern "C" void kernel_launch(void* const* d_in, const int* in_sizes, int n_in,
                              void* d_out, int out_size)
{
    const float2* x    = (const float2*)d_in[0];
    const float*  hg0  = (const float*)d_in[1];
    const float*  hg1  = (const float*)d_in[2];
    // d_in[3] = kc0 (regular grid, analytic), d_in[4] = ks0 (== K-1)
    const float*  lc0  = (const float*)d_in[5];
    const float*  lcb0 = (const float*)d_in[6];
    const float*  W0   = (const float*)d_in[7];
    const float*  b0   = (const float*)d_in[8];
    const float*  W1   = (const float*)d_in[9];
    const float*  b1   = (const float*)d_in[10];
    const float*  W2   = (const float*)d_in[11];
    const float*  b2   = (const float*)d_in[12];
    const float*  a0   = (const float*)d_in[13];
    const float*  a1   = (const float*)d_in[14];
    const float*  a2   = (const float*)d_in[15];
    float* out = (float*)d_out;

    const int n = in_sizes[0] / 2;
    const int ntiles = (n + 31) / 32;
    int grid = 444;                       // 148 SMs x 3 blocks
    int maxg = (ntiles + 3) / 4;
    if (grid > maxg) grid = maxg;

    cudaFuncSetAttribute(rbf_mma_kernel, cudaFuncAttributeMaxDynamicSharedMemorySize, SMEM_BYTES);
    rbf_mma_kernel<<<grid, 128, SMEM_BYTES>>>(x, hg0, hg1, lc0, lcb0,
                                              W0, b0, W1, b1, W2, b2,
                                              a0, a1, a2, out, n, ntiles);
}

// round 14
// speedup vs baseline: 1.5170x; 1.0320x over previous
#include <cuda_runtime.h>
#include <cuda_fp16.h>
#include <math.h>
#include <stdint.h>

typedef uint32_t u32;
typedef unsigned long long u64;

#define LC 20
#define KGRID 1024

// ---- dynamic smem layout (byte offsets) ----
#define OFF_A0H 0          // 128 rows * 20 u32 (stride 80B) = 10240 (hi tile only)
#define OFF_B0  10240      // 2kc*8nt*32lane * uint2 = 4096  (fp16)
#define OFF_B1F 14336      // 4kc*8nt*32lane * uint2 = 8192  (fp16)
#define OFF_W2  22528      // 64 * float4
#define OFF_B1P 23552      // 32 * float2
#define OFF_HG0 23808      // 512 floats
#define OFF_SC  25856      // 3 floats
#define SMEM_BYTES 25872

// pack two floats into f16x2 (v0 -> lower half), RN
__device__ __forceinline__ u32 packh(float v0, float v1) {
    u32 h;
    asm("cvt.rn.f16x2.f32 %0, %1, %2;" : "=r"(h) : "f"(v1), "f"(v0));
    return h;
}

// packed f32x2 helpers
__device__ __forceinline__ u64 pk2(float a, float b) {
    u64 r; asm("mov.b64 %0, {%1, %2};" : "=l"(r) : "f"(a), "f"(b)); return r;
}
__device__ __forceinline__ void upk2(u64 v, float &a, float &b) {
    asm("mov.b64 {%0, %1}, %2;" : "=f"(a), "=f"(b) : "l"(v));
}
__device__ __forceinline__ void ffma2(u64 &acc, u64 a, u64 b) {
    asm("fma.rn.f32x2 %0, %1, %2, %0;" : "+l"(acc) : "l"(a), "l"(b));
}

__device__ __forceinline__ void mma16816(float d[4], const u32 a[4], u32 b0, u32 b1) {
    asm volatile(
        "mma.sync.aligned.m16n8k16.row.col.f32.f16.f16.f32 "
        "{%0,%1,%2,%3}, {%4,%5,%6,%7}, {%8,%9}, {%0,%1,%2,%3};"
        : "+f"(d[0]), "+f"(d[1]), "+f"(d[2]), "+f"(d[3])
        : "r"(a[0]), "r"(a[1]), "r"(a[2]), "r"(a[3]), "r"(b0), "r"(b1));
}

// ---- feature gather: RBF-bilinear (regular grid) + 2 hashgrid levels ----
__device__ __forceinline__ void gather_feats(float2 p,
                                             const float* __restrict__ lc0,
                                             const float* __restrict__ hg1,
                                             const float* shg0,
                                             float* h0)
{
    {
        float gx = p.x * 1023.0f, gy = p.y * 1023.0f;
        int ix = (int)floorf(gx); ix = max(0, min(ix, 1022));
        int iy = (int)floorf(gy); iy = max(0, min(iy, 1022));
        float fx = gx - (float)ix, fy = gy - (float)iy;
        // weights sum to 1 (+-1ulp); reference's normalize shifts them ~1e-7 -> dropped
        float w00 = (1.0f - fx) * (1.0f - fy);
        float w01 = (1.0f - fx) * fy;
        float w10 = fx * (1.0f - fy);
        float w11 = fx * fy;
        u64 W00 = pk2(w00, w00), W01 = pk2(w01, w01);
        u64 W10 = pk2(w10, w10), W11 = pk2(w11, w11);
        const float4* r0 = (const float4*)(lc0 + (size_t)(ix * KGRID + iy) * LC);
        const float4* r1 = (const float4*)(lc0 + (size_t)((ix + 1) * KGRID + iy) * LC);
        #pragma unroll
        for (int q = 0; q < 5; q++) {
            float4 c00 = r0[q], c01 = r0[q + 5];
            float4 c10 = r1[q], c11 = r1[q + 5];
            u64 a01 = 0ull, a23 = 0ull;
            ffma2(a01, pk2(c00.x, c00.y), W00); ffma2(a23, pk2(c00.z, c00.w), W00);
            ffma2(a01, pk2(c01.x, c01.y), W01); ffma2(a23, pk2(c01.z, c01.w), W01);
            ffma2(a01, pk2(c10.x, c10.y), W10); ffma2(a23, pk2(c10.z, c10.w), W10);
            ffma2(a01, pk2(c11.x, c11.y), W11); ffma2(a23, pk2(c11.z, c11.w), W11);
            upk2(a01, h0[4 * q + 0], h0[4 * q + 1]);
            upk2(a23, h0[4 * q + 2], h0[4 * q + 3]);
        }
    }
    {
        float gx = p.x * 15.0f, gy = p.y * 15.0f;
        int ix = (int)floorf(gx); ix = max(0, min(ix, 14));
        int iy = (int)floorf(gy); iy = max(0, min(iy, 14));
        float fx = gx - (float)ix, fy = gy - (float)iy;
        float w00 = (1.0f - fx) * (1.0f - fy), w01 = (1.0f - fx) * fy;
        float w10 = fx * (1.0f - fy),          w11 = fx * fy;
        const float2* t = (const float2*)shg0;
        float2 c00 = t[ix * 16 + iy],       c01 = t[ix * 16 + iy + 1];
        float2 c10 = t[(ix + 1) * 16 + iy], c11 = t[(ix + 1) * 16 + iy + 1];
        h0[20] = w00 * c00.x + w01 * c01.x + w10 * c10.x + w11 * c11.x;
        h0[21] = w00 * c00.y + w01 * c01.y + w10 * c10.y + w11 * c11.y;
    }
    {
        float gx = p.x * 2047.0f, gy = p.y * 2047.0f;
        int ix = (int)floorf(gx); ix = max(0, min(ix, 2046));
        int iy = (int)floorf(gy); iy = max(0, min(iy, 2046));
        float fx = gx - (float)ix, fy = gy - (float)iy;
        float w00 = (1.0f - fx) * (1.0f - fy), w01 = (1.0f - fx) * fy;
        float w10 = fx * (1.0f - fy),          w11 = fx * fy;
        const float2* t = (const float2*)hg1;
        float2 c00 = t[ix * 2048 + iy],       c01 = t[ix * 2048 + iy + 1];
        float2 c10 = t[(ix + 1) * 2048 + iy], c11 = t[(ix + 1) * 2048 + iy + 1];
        h0[22] = w00 * c00.x + w01 * c01.x + w10 * c10.x + w11 * c11.x;
        h0[23] = w00 * c00.y + w01 * c01.y + w10 * c10.y + w11 * c11.y;
    }
}

__global__ void __launch_bounds__(128, 3)
rbf_mma_kernel(const float2* __restrict__ x,
               const float* __restrict__ hg0g, const float* __restrict__ hg1,
               const float* __restrict__ lc0,  const float* __restrict__ lcbg,
               const float* __restrict__ W0g, const float* __restrict__ b0g,
               const float* __restrict__ W1g, const float* __restrict__ b1g,
               const float* __restrict__ W2g, const float* __restrict__ b2g,
               const float* __restrict__ a0g, const float* __restrict__ a1g,
               const float* __restrict__ a2g,
               float* __restrict__ out, int n, int ntiles)
{
    extern __shared__ char base[];
    const int tid = threadIdx.x;
    const int wid = tid >> 5, lane = tid & 31;
    const int g = lane >> 2, t = lane & 3;
    const float a0 = a0g[0], a1 = a1g[0], a2 = a2g[0];

    u32*    sA0h = (u32*)(base + OFF_A0H);
    uint2*  sB0  = (uint2*)(base + OFF_B0);
    uint2*  sB1  = (uint2*)(base + OFF_B1F);
    float4* sW2  = (float4*)(base + OFF_W2);
    float2* sb1p = (float2*)(base + OFF_B1P);
    float*  shg0 = (float*)(base + OFF_HG0);
    float*  ssc  = (float*)(base + OFF_SC);

    // ---- one-time init ----
    for (int k = tid; k < 512; k += 128) shg0[k] = hg0g[k];
    if (tid < 64)
        sW2[tid] = make_float4(a2 * W2g[tid], a2 * W2g[64 + tid], a2 * W2g[128 + tid], 0.0f);
    if (tid < 32) {
        int nt_ = tid >> 2, t_ = tid & 3;
        int c0 = nt_ * 8 + 2 * t_;
        sb1p[tid] = make_float2(a1 * b1g[c0], a1 * b1g[c0 + 1]);
    }
    if (tid < 3) ssc[tid] = a2 * b2g[tid];

    // constant A0 row tail (cols 24..31): bias 1.0 at col 24, zeros elsewhere.
    {
        u32* rowh = sA0h + tid * 20;
        rowh[12] = 0x00003C00u; rowh[13] = 0u; rowh[14] = 0u; rowh[15] = 0u;
        rowh[16] = rowh[17] = rowh[18] = rowh[19] = 0u;
    }

    // B0 fragments (fp16): B0[k][n]; k<24: a0*W0[n][k];
    // k==24: a0*(b0[n]+lcb@W0[n]); else 0
    for (int s = tid; s < 512; s += 128) {
        int ln = s & 31, nt_ = (s >> 5) & 7, kc = s >> 8;
        int gg = ln >> 2, tt = ln & 3;
        int nn = nt_ * 8 + gg;
        int k0 = kc * 16 + 2 * tt;
        float w[4];
        #pragma unroll
        for (int q = 0; q < 4; q++) {
            int k = k0 + (q >> 1) * 8 + (q & 1);
            float v;
            if (k < 24) v = a0 * W0g[nn * 24 + k];
            else if (k == 24) {
                float acc = b0g[nn];
                for (int kk = 0; kk < 24; kk++) acc += lcbg[kk] * W0g[nn * 24 + kk];
                v = a0 * acc;
            } else v = 0.0f;
            w[q] = v;
        }
        sB0[s] = make_uint2(packh(w[0], w[1]), packh(w[2], w[3]));
    }
    // B1 fragments (fp16): B1[k][n] = a1*W1[n][k]
    for (int s = tid; s < 1024; s += 128) {
        int ln = s & 31, nt_ = (s >> 5) & 7, kc = s >> 8;
        int gg = ln >> 2, tt = ln & 3;
        int nn = nt_ * 8 + gg;
        int k0 = kc * 16 + 2 * tt;
        float w0v = a1 * W1g[nn * 64 + k0];
        float w1v = a1 * W1g[nn * 64 + k0 + 1];
        float w2v = a1 * W1g[nn * 64 + k0 + 8];
        float w3v = a1 * W1g[nn * 64 + k0 + 9];
        sB1[s] = make_uint2(packh(w0v, w1v), packh(w2v, w3v));
    }
    __syncthreads();

    const float c0s = ssc[0], c1s = ssc[1], c2s = ssc[2];
    const int gw = blockIdx.x * 4 + wid;
    const int nw = gridDim.x * 4;
    const int rbase = wid * 32;

    for (int tile = gw; tile < ntiles; tile += nw) {
        int i = tile * 32 + lane;
        int ii = (i < n) ? i : (n - 1);

        float h0[24];
        gather_feats(x[ii], lc0, hg1, shg0, h0);

        // ---- write this lane's A0 row cols 0..23, fp16 RN (hi only) ----
        {
            u32 rh[12];
            #pragma unroll
            for (int q = 0; q < 12; q++)
                rh[q] = packh(h0[2 * q], h0[2 * q + 1]);
            uint4* rh4 = (uint4*)(sA0h + (rbase + lane) * 20);
            #pragma unroll
            for (int q = 0; q < 3; q++)
                rh4[q] = make_uint4(rh[4 * q], rh[4 * q + 1], rh[4 * q + 2], rh[4 * q + 3]);
        }
        __syncwarp();

        // ---- load A0 fragments (hi only) for BOTH m halves ----
        u32 Ah[2][2][4];   // [m][kc][4]
        #pragma unroll
        for (int m = 0; m < 2; m++) {
            int ridx = (rbase + 16 * m + g) * 20 + t;
            #pragma unroll
            for (int kc = 0; kc < 2; kc++) {
                Ah[m][kc][0] = sA0h[ridx + 8 * kc];
                Ah[m][kc][1] = sA0h[ridx + 8 * kc + 160];
                Ah[m][kc][2] = sA0h[ridx + 8 * kc + 4];
                Ah[m][kc][3] = sA0h[ridx + 8 * kc + 164];
            }
        }
        __syncwarp();   // all frag reads done before next tile's writes

        // ---- layer 0: nt-pairs x both m = 4 independent chains, A hi-only ----
        u32 A1h[2][4][4];   // [m][kc1][4]  (h1 kept hi-only for layer 1 too)
        #pragma unroll
        for (int ntp = 0; ntp < 4; ntp++) {
            float d[2][2][4];             // [ntq][m][4]
            #pragma unroll
            for (int q_ = 0; q_ < 2; q_++)
                #pragma unroll
                for (int m = 0; m < 2; m++)
                    d[q_][m][0] = d[q_][m][1] = d[q_][m][2] = d[q_][m][3] = 0.f;
            #pragma unroll
            for (int kc = 0; kc < 2; kc++) {
                uint2 Ba = sB0[(kc * 8 + 2 * ntp) * 32 + lane];
                uint2 Bb = sB0[(kc * 8 + 2 * ntp + 1) * 32 + lane];
                mma16816(d[0][0], Ah[0][kc], Ba.x, Ba.y);
                mma16816(d[1][0], Ah[0][kc], Bb.x, Bb.y);
                mma16816(d[0][1], Ah[1][kc], Ba.x, Ba.y);
                mma16816(d[1][1], Ah[1][kc], Bb.x, Bb.y);
            }
            #pragma unroll
            for (int q_ = 0; q_ < 2; q_++) {
                int nt = 2 * ntp + q_;
                int kc1 = nt >> 1, hf = nt & 1;
                #pragma unroll
                for (int m = 0; m < 2; m++) {
                    float v0 = fmaxf(d[q_][m][0], 0.f), v1 = fmaxf(d[q_][m][1], 0.f);
                    float v2 = fmaxf(d[q_][m][2], 0.f), v3 = fmaxf(d[q_][m][3], 0.f);
                    A1h[m][kc1][hf ? 2 : 0] = packh(v0, v1);
                    A1h[m][kc1][hf ? 3 : 1] = packh(v2, v3);
                }
            }
        }

        // ---- layer 1 + fused output layer, A hi-only, 4-chain interleave ----
        float o[2][2][3];
        #pragma unroll
        for (int m = 0; m < 2; m++)
            #pragma unroll
            for (int r = 0; r < 2; r++)
                o[m][r][0] = o[m][r][1] = o[m][r][2] = 0.0f;

        #pragma unroll
        for (int ntp = 0; ntp < 4; ntp++) {
            float d[2][2][4];
            #pragma unroll
            for (int q_ = 0; q_ < 2; q_++)
                #pragma unroll
                for (int m = 0; m < 2; m++)
                    d[q_][m][0] = d[q_][m][1] = d[q_][m][2] = d[q_][m][3] = 0.f;
            #pragma unroll
            for (int kc = 0; kc < 4; kc++) {
                uint2 Ba = sB1[(kc * 8 + 2 * ntp) * 32 + lane];
                uint2 Bb = sB1[(kc * 8 + 2 * ntp + 1) * 32 + lane];
                mma16816(d[0][0], A1h[0][kc], Ba.x, Ba.y);
                mma16816(d[1][0], A1h[0][kc], Bb.x, Bb.y);
                mma16816(d[0][1], A1h[1][kc], Ba.x, Ba.y);
                mma16816(d[1][1], A1h[1][kc], Bb.x, Bb.y);
            }
            #pragma unroll
            for (int q_ = 0; q_ < 2; q_++) {
                int nt = 2 * ntp + q_;
                float2 bp = sb1p[nt * 4 + t];
                float4 wa = sW2[nt * 8 + 2 * t];
                float4 wb = sW2[nt * 8 + 2 * t + 1];
                #pragma unroll
                for (int m = 0; m < 2; m++) {
                    float v0 = fmaxf(d[q_][m][0] + bp.x, 0.f);
                    float v1 = fmaxf(d[q_][m][1] + bp.y, 0.f);
                    float v2 = fmaxf(d[q_][m][2] + bp.x, 0.f);
                    float v3 = fmaxf(d[q_][m][3] + bp.y, 0.f);
                    o[m][0][0] += v0 * wa.x + v1 * wb.x;
                    o[m][0][1] += v0 * wa.y + v1 * wb.y;
                    o[m][0][2] += v0 * wa.z + v1 * wb.z;
                    o[m][1][0] += v2 * wa.x + v3 * wb.x;
                    o[m][1][1] += v2 * wa.y + v3 * wb.y;
                    o[m][1][2] += v2 * wa.z + v3 * wb.z;
                }
            }
        }

        // reduce partials across the 4 lanes of each group (cols are t-partitioned)
        #pragma unroll
        for (int m = 0; m < 2; m++)
            #pragma unroll
            for (int r = 0; r < 2; r++)
                #pragma unroll
                for (int c = 0; c < 3; c++) {
                    float v = o[m][r][c];
                    v += __shfl_xor_sync(0xFFFFFFFFu, v, 1);
                    v += __shfl_xor_sync(0xFFFFFFFFu, v, 2);
                    o[m][r][c] = v;
                }

        if (t == 0) {
            #pragma unroll
            for (int m = 0; m < 2; m++)
                #pragma unroll
                for (int r = 0; r < 2; r++) {
                    int idx = tile * 32 + 16 * m + 8 * r + g;
                    if (idx < n) {
                        out[3 * idx + 0] = o[m][r][0] + c0s;
                        out[3 * idx + 1] = o[m][r][1] + c1s;
                        out[3 * idx + 2] = o[m][r][2] + c2s;
                    }
                }
        }
    }
}

extern "C" void kernel_launch(void* const* d_in, const int* in_sizes, int n_in,
                              void* d_out, int out_size)
{
    const float2* x    = (const float2*)d_in[0];
    const float*  hg0  = (const float*)d_in[1];
    const float*  hg1  = (const float*)d_in[2];
    // d_in[3] = kc0 (regular grid, analytic), d_in[4] = ks0 (== K-1)
    const float*  lc0  = (const float*)d_in[5];
    const float*  lcb0 = (const float*)d_in[6];
    const float*  W0   = (const float*)d_in[7];
    const float*  b0   = (const float*)d_in[8];
    const float*  W1   = (const float*)d_in[9];
    const float*  b1   = (const float*)d_in[10];
    const float*  W2   = (const float*)d_in[11];
    const float*  b2   = (const float*)d_in[12];
    const float*  a0   = (const float*)d_in[13];
    const float*  a1   = (const float*)d_in[14];
    const float*  a2   = (const float*)d_in[15];
    float* out = (float*)d_out;

    const int n = in_sizes[0] / 2;
    const int ntiles = (n + 31) / 32;
    int grid = 444;                       // 148 SMs x 3 blocks
    int maxg = (ntiles + 3) / 4;
    if (grid > maxg) grid = maxg;

    cudaFuncSetAttribute(rbf_mma_kernel, cudaFuncAttributeMaxDynamicSharedMemorySize, SMEM_BYTES);
    rbf_mma_kernel<<<grid, 128, SMEM_BYTES>>>(x, hg0, hg1, lc0, lcb0,
                                              W0, b0, W1, b1, W2, b2,
                                              a0, a1, a2, out, n, ntiles);
}

// round 15
// speedup vs baseline: 1.5338x; 1.0111x over previous
#include <cuda_runtime.h>
#include <cuda_fp16.h>
#include <math.h>
#include <stdint.h>

typedef uint32_t u32;
typedef unsigned long long u64;

#define LC 20
#define KGRID 1024

// ---- dynamic smem layout (byte offsets) ----
#define OFF_A0H 0          // 128 rows * 20 u32 (stride 80B) = 10240 (hi tile only)
#define OFF_B0  10240      // 2kc*8nt*32lane * uint2 = 4096  (fp16)
#define OFF_B1F 14336      // 4kc*8nt*32lane * uint2 = 8192  (fp16)
#define OFF_W2  22528      // 64 * float4
#define OFF_B1P 23552      // 32 * float2
#define OFF_HG0 23808      // 512 floats
#define OFF_SC  25856      // 3 floats
#define SMEM_BYTES 25872

// pack two floats into f16x2 (v0 -> lower half), RN
__device__ __forceinline__ u32 packh(float v0, float v1) {
    u32 h;
    asm("cvt.rn.f16x2.f32 %0, %1, %2;" : "=r"(h) : "f"(v1), "f"(v0));
    return h;
}

// packed f32x2 helpers
__device__ __forceinline__ u64 pk2(float a, float b) {
    u64 r; asm("mov.b64 %0, {%1, %2};" : "=l"(r) : "f"(a), "f"(b)); return r;
}
__device__ __forceinline__ void upk2(u64 v, float &a, float &b) {
    asm("mov.b64 {%0, %1}, %2;" : "=f"(a), "=f"(b) : "l"(v));
}
__device__ __forceinline__ void ffma2(u64 &acc, u64 a, u64 b) {
    asm("fma.rn.f32x2 %0, %1, %2, %0;" : "+l"(acc) : "l"(a), "l"(b));
}

__device__ __forceinline__ void mma16816(float d[4], const u32 a[4], u32 b0, u32 b1) {
    asm volatile(
        "mma.sync.aligned.m16n8k16.row.col.f32.f16.f16.f32 "
        "{%0,%1,%2,%3}, {%4,%5,%6,%7}, {%8,%9}, {%0,%1,%2,%3};"
        : "+f"(d[0]), "+f"(d[1]), "+f"(d[2]), "+f"(d[3])
        : "r"(a[0]), "r"(a[1]), "r"(a[2]), "r"(a[3]), "r"(b0), "r"(b1));
}

// ---- feature gather: RBF-bilinear (regular grid) + 2 hashgrid levels ----
__device__ __forceinline__ void gather_feats(float2 p,
                                             const float* __restrict__ lc0,
                                             const float* __restrict__ hg1,
                                             const float* shg0,
                                             float* h0)
{
    {
        float gx = p.x * 1023.0f, gy = p.y * 1023.0f;
        int ix = (int)floorf(gx); ix = max(0, min(ix, 1022));
        int iy = (int)floorf(gy); iy = max(0, min(iy, 1022));
        float fx = gx - (float)ix, fy = gy - (float)iy;
        // weights sum to 1 (+-1ulp); reference's normalize shifts them ~1e-7 -> dropped
        float w00 = (1.0f - fx) * (1.0f - fy);
        float w01 = (1.0f - fx) * fy;
        float w10 = fx * (1.0f - fy);
        float w11 = fx * fy;
        u64 W00 = pk2(w00, w00), W01 = pk2(w01, w01);
        u64 W10 = pk2(w10, w10), W11 = pk2(w11, w11);
        const float4* r0 = (const float4*)(lc0 + (size_t)(ix * KGRID + iy) * LC);
        const float4* r1 = (const float4*)(lc0 + (size_t)((ix + 1) * KGRID + iy) * LC);
        #pragma unroll
        for (int q = 0; q < 5; q++) {
            float4 c00 = r0[q], c01 = r0[q + 5];
            float4 c10 = r1[q], c11 = r1[q + 5];
            u64 a01 = 0ull, a23 = 0ull;
            ffma2(a01, pk2(c00.x, c00.y), W00); ffma2(a23, pk2(c00.z, c00.w), W00);
            ffma2(a01, pk2(c01.x, c01.y), W01); ffma2(a23, pk2(c01.z, c01.w), W01);
            ffma2(a01, pk2(c10.x, c10.y), W10); ffma2(a23, pk2(c10.z, c10.w), W10);
            ffma2(a01, pk2(c11.x, c11.y), W11); ffma2(a23, pk2(c11.z, c11.w), W11);
            upk2(a01, h0[4 * q + 0], h0[4 * q + 1]);
            upk2(a23, h0[4 * q + 2], h0[4 * q + 3]);
        }
    }
    {
        float gx = p.x * 15.0f, gy = p.y * 15.0f;
        int ix = (int)floorf(gx); ix = max(0, min(ix, 14));
        int iy = (int)floorf(gy); iy = max(0, min(iy, 14));
        float fx = gx - (float)ix, fy = gy - (float)iy;
        float w00 = (1.0f - fx) * (1.0f - fy), w01 = (1.0f - fx) * fy;
        float w10 = fx * (1.0f - fy),          w11 = fx * fy;
        const float2* t = (const float2*)shg0;
        float2 c00 = t[ix * 16 + iy],       c01 = t[ix * 16 + iy + 1];
        float2 c10 = t[(ix + 1) * 16 + iy], c11 = t[(ix + 1) * 16 + iy + 1];
        h0[20] = w00 * c00.x + w01 * c01.x + w10 * c10.x + w11 * c11.x;
        h0[21] = w00 * c00.y + w01 * c01.y + w10 * c10.y + w11 * c11.y;
    }
    {
        float gx = p.x * 2047.0f, gy = p.y * 2047.0f;
        int ix = (int)floorf(gx); ix = max(0, min(ix, 2046));
        int iy = (int)floorf(gy); iy = max(0, min(iy, 2046));
        float fx = gx - (float)ix, fy = gy - (float)iy;
        float w00 = (1.0f - fx) * (1.0f - fy), w01 = (1.0f - fx) * fy;
        float w10 = fx * (1.0f - fy),          w11 = fx * fy;
        const float2* t = (const float2*)hg1;
        float2 c00 = t[ix * 2048 + iy],       c01 = t[ix * 2048 + iy + 1];
        float2 c10 = t[(ix + 1) * 2048 + iy], c11 = t[(ix + 1) * 2048 + iy + 1];
        h0[22] = w00 * c00.x + w01 * c01.x + w10 * c10.x + w11 * c11.x;
        h0[23] = w00 * c00.y + w01 * c01.y + w10 * c10.y + w11 * c11.y;
    }
}

__global__ void __launch_bounds__(128, 4)
rbf_mma_kernel(const float2* __restrict__ x,
               const float* __restrict__ hg0g, const float* __restrict__ hg1,
               const float* __restrict__ lc0,  const float* __restrict__ lcbg,
               const float* __restrict__ W0g, const float* __restrict__ b0g,
               const float* __restrict__ W1g, const float* __restrict__ b1g,
               const float* __restrict__ W2g, const float* __restrict__ b2g,
               const float* __restrict__ a0g, const float* __restrict__ a1g,
               const float* __restrict__ a2g,
               float* __restrict__ out, int n, int ntiles)
{
    extern __shared__ char base[];
    const int tid = threadIdx.x;
    const int wid = tid >> 5, lane = tid & 31;
    const int g = lane >> 2, t = lane & 3;
    const float a0 = a0g[0], a1 = a1g[0], a2 = a2g[0];

    u32*    sA0h = (u32*)(base + OFF_A0H);
    uint2*  sB0  = (uint2*)(base + OFF_B0);
    uint2*  sB1  = (uint2*)(base + OFF_B1F);
    float4* sW2  = (float4*)(base + OFF_W2);
    float2* sb1p = (float2*)(base + OFF_B1P);
    float*  shg0 = (float*)(base + OFF_HG0);
    float*  ssc  = (float*)(base + OFF_SC);

    // ---- one-time init ----
    for (int k = tid; k < 512; k += 128) shg0[k] = hg0g[k];
    if (tid < 64)
        sW2[tid] = make_float4(a2 * W2g[tid], a2 * W2g[64 + tid], a2 * W2g[128 + tid], 0.0f);
    if (tid < 32) {
        int nt_ = tid >> 2, t_ = tid & 3;
        int c0 = nt_ * 8 + 2 * t_;
        sb1p[tid] = make_float2(a1 * b1g[c0], a1 * b1g[c0 + 1]);
    }
    if (tid < 3) ssc[tid] = a2 * b2g[tid];

    // constant A0 row tail (cols 24..31): bias 1.0 at col 24, zeros elsewhere.
    {
        u32* rowh = sA0h + tid * 20;
        rowh[12] = 0x00003C00u; rowh[13] = 0u; rowh[14] = 0u; rowh[15] = 0u;
        rowh[16] = rowh[17] = rowh[18] = rowh[19] = 0u;
    }

    // B0 fragments (fp16): B0[k][n]; k<24: a0*W0[n][k];
    // k==24: a0*(b0[n]+lcb@W0[n]); else 0
    for (int s = tid; s < 512; s += 128) {
        int ln = s & 31, nt_ = (s >> 5) & 7, kc = s >> 8;
        int gg = ln >> 2, tt = ln & 3;
        int nn = nt_ * 8 + gg;
        int k0 = kc * 16 + 2 * tt;
        float w[4];
        #pragma unroll
        for (int q = 0; q < 4; q++) {
            int k = k0 + (q >> 1) * 8 + (q & 1);
            float v;
            if (k < 24) v = a0 * W0g[nn * 24 + k];
            else if (k == 24) {
                float acc = b0g[nn];
                for (int kk = 0; kk < 24; kk++) acc += lcbg[kk] * W0g[nn * 24 + kk];
                v = a0 * acc;
            } else v = 0.0f;
            w[q] = v;
        }
        sB0[s] = make_uint2(packh(w[0], w[1]), packh(w[2], w[3]));
    }
    // B1 fragments (fp16): B1[k][n] = a1*W1[n][k]
    for (int s = tid; s < 1024; s += 128) {
        int ln = s & 31, nt_ = (s >> 5) & 7, kc = s >> 8;
        int gg = ln >> 2, tt = ln & 3;
        int nn = nt_ * 8 + gg;
        int k0 = kc * 16 + 2 * tt;
        float w0v = a1 * W1g[nn * 64 + k0];
        float w1v = a1 * W1g[nn * 64 + k0 + 1];
        float w2v = a1 * W1g[nn * 64 + k0 + 8];
        float w3v = a1 * W1g[nn * 64 + k0 + 9];
        sB1[s] = make_uint2(packh(w0v, w1v), packh(w2v, w3v));
    }
    __syncthreads();

    const float c0s = ssc[0], c1s = ssc[1], c2s = ssc[2];
    const int gw = blockIdx.x * 4 + wid;
    const int nw = gridDim.x * 4;
    const int rbase = wid * 32;

    for (int tile = gw; tile < ntiles; tile += nw) {
        int i = tile * 32 + lane;
        int ii = (i < n) ? i : (n - 1);

        float h0[24];
        gather_feats(x[ii], lc0, hg1, shg0, h0);

        // ---- write this lane's A0 row cols 0..23, fp16 RN (hi only) ----
        {
            u32 rh[12];
            #pragma unroll
            for (int q = 0; q < 12; q++)
                rh[q] = packh(h0[2 * q], h0[2 * q + 1]);
            uint4* rh4 = (uint4*)(sA0h + (rbase + lane) * 20);
            #pragma unroll
            for (int q = 0; q < 3; q++)
                rh4[q] = make_uint4(rh[4 * q], rh[4 * q + 1], rh[4 * q + 2], rh[4 * q + 3]);
        }
        __syncwarp();

        // ---- load A0 fragments (hi only) for BOTH m halves ----
        u32 Ah[2][2][4];   // [m][kc][4]
        #pragma unroll
        for (int m = 0; m < 2; m++) {
            int ridx = (rbase + 16 * m + g) * 20 + t;
            #pragma unroll
            for (int kc = 0; kc < 2; kc++) {
                Ah[m][kc][0] = sA0h[ridx + 8 * kc];
                Ah[m][kc][1] = sA0h[ridx + 8 * kc + 160];
                Ah[m][kc][2] = sA0h[ridx + 8 * kc + 4];
                Ah[m][kc][3] = sA0h[ridx + 8 * kc + 164];
            }
        }
        __syncwarp();   // all frag reads done before next tile's writes

        // ---- layer 0: nt-pairs x both m = 4 independent chains, A hi-only ----
        u32 A1h[2][4][4];   // [m][kc1][4]  (h1 kept hi-only for layer 1 too)
        #pragma unroll
        for (int ntp = 0; ntp < 4; ntp++) {
            float d[2][2][4];             // [ntq][m][4]
            #pragma unroll
            for (int q_ = 0; q_ < 2; q_++)
                #pragma unroll
                for (int m = 0; m < 2; m++)
                    d[q_][m][0] = d[q_][m][1] = d[q_][m][2] = d[q_][m][3] = 0.f;
            #pragma unroll
            for (int kc = 0; kc < 2; kc++) {
                uint2 Ba = sB0[(kc * 8 + 2 * ntp) * 32 + lane];
                uint2 Bb = sB0[(kc * 8 + 2 * ntp + 1) * 32 + lane];
                mma16816(d[0][0], Ah[0][kc], Ba.x, Ba.y);
                mma16816(d[1][0], Ah[0][kc], Bb.x, Bb.y);
                mma16816(d[0][1], Ah[1][kc], Ba.x, Ba.y);
                mma16816(d[1][1], Ah[1][kc], Bb.x, Bb.y);
            }
            #pragma unroll
            for (int q_ = 0; q_ < 2; q_++) {
                int nt = 2 * ntp + q_;
                int kc1 = nt >> 1, hf = nt & 1;
                #pragma unroll
                for (int m = 0; m < 2; m++) {
                    float v0 = fmaxf(d[q_][m][0], 0.f), v1 = fmaxf(d[q_][m][1], 0.f);
                    float v2 = fmaxf(d[q_][m][2], 0.f), v3 = fmaxf(d[q_][m][3], 0.f);
                    A1h[m][kc1][hf ? 2 : 0] = packh(v0, v1);
                    A1h[m][kc1][hf ? 3 : 1] = packh(v2, v3);
                }
            }
        }

        // ---- layer 1 + fused output layer, A hi-only, 4-chain interleave ----
        float o[2][2][3];
        #pragma unroll
        for (int m = 0; m < 2; m++)
            #pragma unroll
            for (int r = 0; r < 2; r++)
                o[m][r][0] = o[m][r][1] = o[m][r][2] = 0.0f;

        #pragma unroll
        for (int ntp = 0; ntp < 4; ntp++) {
            float d[2][2][4];
            #pragma unroll
            for (int q_ = 0; q_ < 2; q_++)
                #pragma unroll
                for (int m = 0; m < 2; m++)
                    d[q_][m][0] = d[q_][m][1] = d[q_][m][2] = d[q_][m][3] = 0.f;
            #pragma unroll
            for (int kc = 0; kc < 4; kc++) {
                uint2 Ba = sB1[(kc * 8 + 2 * ntp) * 32 + lane];
                uint2 Bb = sB1[(kc * 8 + 2 * ntp + 1) * 32 + lane];
                mma16816(d[0][0], A1h[0][kc], Ba.x, Ba.y);
                mma16816(d[1][0], A1h[0][kc], Bb.x, Bb.y);
                mma16816(d[0][1], A1h[1][kc], Ba.x, Ba.y);
                mma16816(d[1][1], A1h[1][kc], Bb.x, Bb.y);
            }
            #pragma unroll
            for (int q_ = 0; q_ < 2; q_++) {
                int nt = 2 * ntp + q_;
                float2 bp = sb1p[nt * 4 + t];
                float4 wa = sW2[nt * 8 + 2 * t];
                float4 wb = sW2[nt * 8 + 2 * t + 1];
                #pragma unroll
                for (int m = 0; m < 2; m++) {
                    float v0 = fmaxf(d[q_][m][0] + bp.x, 0.f);
                    float v1 = fmaxf(d[q_][m][1] + bp.y, 0.f);
                    float v2 = fmaxf(d[q_][m][2] + bp.x, 0.f);
                    float v3 = fmaxf(d[q_][m][3] + bp.y, 0.f);
                    o[m][0][0] += v0 * wa.x + v1 * wb.x;
                    o[m][0][1] += v0 * wa.y + v1 * wb.y;
                    o[m][0][2] += v0 * wa.z + v1 * wb.z;
                    o[m][1][0] += v2 * wa.x + v3 * wb.x;
                    o[m][1][1] += v2 * wa.y + v3 * wb.y;
                    o[m][1][2] += v2 * wa.z + v3 * wb.z;
                }
            }
        }

        // reduce partials across the 4 lanes of each group (cols are t-partitioned)
        #pragma unroll
        for (int m = 0; m < 2; m++)
            #pragma unroll
            for (int r = 0; r < 2; r++)
                #pragma unroll
                for (int c = 0; c < 3; c++) {
                    float v = o[m][r][c];
                    v += __shfl_xor_sync(0xFFFFFFFFu, v, 1);
                    v += __shfl_xor_sync(0xFFFFFFFFu, v, 2);
                    o[m][r][c] = v;
                }

        if (t == 0) {
            #pragma unroll
            for (int m = 0; m < 2; m++)
                #pragma unroll
                for (int r = 0; r < 2; r++) {
                    int idx = tile * 32 + 16 * m + 8 * r + g;
                    if (idx < n) {
                        out[3 * idx + 0] = o[m][r][0] + c0s;
                        out[3 * idx + 1] = o[m][r][1] + c1s;
                        out[3 * idx + 2] = o[m][r][2] + c2s;
                    }
                }
        }
    }
}

extern "C" void kernel_launch(void* const* d_in, const int* in_sizes, int n_in,
                              void* d_out, int out_size)
{
    const float2* x    = (const float2*)d_in[0];
    const float*  hg0  = (const float*)d_in[1];
    const float*  hg1  = (const float*)d_in[2];
    // d_in[3] = kc0 (regular grid, analytic), d_in[4] = ks0 (== K-1)
    const float*  lc0  = (const float*)d_in[5];
    const float*  lcb0 = (const float*)d_in[6];
    const float*  W0   = (const float*)d_in[7];
    const float*  b0   = (const float*)d_in[8];
    const float*  W1   = (const float*)d_in[9];
    const float*  b1   = (const float*)d_in[10];
    const float*  W2   = (const float*)d_in[11];
    const float*  b2   = (const float*)d_in[12];
    const float*  a0   = (const float*)d_in[13];
    const float*  a1   = (const float*)d_in[14];
    const float*  a2   = (const float*)d_in[15];
    float* out = (float*)d_out;

    const int n = in_sizes[0] / 2;
    const int ntiles = (n + 31) / 32;
    int grid = 592;                       // 148 SMs x 4 blocks
    int maxg = (ntiles + 3) / 4;
    if (grid > maxg) grid = maxg;

    cudaFuncSetAttribute(rbf_mma_kernel, cudaFuncAttributeMaxDynamicSharedMemorySize, SMEM_BYTES);
    rbf_mma_kernel<<<grid, 128, SMEM_BYTES>>>(x, hg0, hg1, lc0, lcb0,
                                              W0, b0, W1, b1, W2, b2,
                                              a0, a1, a2, out, n, ntiles);
}